// round 14
// baseline (speedup 1.0000x reference)
#include <cuda_runtime.h>
#include <cuda_fp16.h>
#include <cstdint>
#include <cstddef>

#define G   256
#define CH  128
#define HD  64
#define NTHREADS 256

// ---- smem byte offsets (tiles: [row][64 halves] = 128B rows, SW128 swizzle) ----
#define SB_OFF  0                        // bias: 192 floats
#define XT_OFF  1024                     // 2 x [256][64] fp16 (ch-chunks) = 64 KB
#define WT_OFF  (XT_OFF + 2*32768)       // 2 x [192][64] fp16 (ch-chunks) = 48 KB
#define K_OFF   (WT_OFF + 2*24576)       // [256][64] fp16                 = 32 KB
#define V_OFF   (K_OFF  + 32768)         // [256][64] fp16                 = 32 KB
#define SMEM_BYTES (V_OFF + 32768)       // 181248

#define SWZ(o) ((o) ^ (((o) >> 3) & 0x70))
#define ESC2 0.12751744f                 // (1/sqrt(128)) * log2(e)

__device__ __forceinline__ uint32_t smem_u32(const void* p) {
    uint32_t a;
    asm("{ .reg .u64 t; cvta.to.shared.u64 t, %1; cvt.u32.u64 %0, t; }" : "=r"(a) : "l"(p));
    return a;
}
__device__ __forceinline__ uint32_t h2u(float a, float b) {
    __half2 h = __floats2half2_rn(a, b);
    return *reinterpret_cast<uint32_t*>(&h);
}
__device__ __forceinline__ float ex2f(float x) {
    float r; asm("ex2.approx.f32 %0, %1;" : "=f"(r) : "f"(x)); return r;
}
__device__ __forceinline__ void ldsm4(uint32_t* r, uint32_t addr) {
    asm volatile("ldmatrix.sync.aligned.m8n8.x4.shared.b16 {%0,%1,%2,%3}, [%4];"
                 : "=r"(r[0]), "=r"(r[1]), "=r"(r[2]), "=r"(r[3]) : "r"(addr));
}
__device__ __forceinline__ void ldsm4t(uint32_t* r, uint32_t addr) {
    asm volatile("ldmatrix.sync.aligned.m8n8.x4.trans.shared.b16 {%0,%1,%2,%3}, [%4];"
                 : "=r"(r[0]), "=r"(r[1]), "=r"(r[2]), "=r"(r[3]) : "r"(addr));
}
__device__ __forceinline__ void mma16816(float* d, const uint32_t* a, uint32_t b0, uint32_t b1) {
    asm volatile("mma.sync.aligned.m16n8k16.row.col.f32.f16.f16.f32 "
        "{%0,%1,%2,%3}, {%4,%5,%6,%7}, {%8,%9}, {%0,%1,%2,%3};"
        : "+f"(d[0]), "+f"(d[1]), "+f"(d[2]), "+f"(d[3])
        : "r"(a[0]), "r"(a[1]), "r"(a[2]), "r"(a[3]), "r"(b0), "r"(b1));
}
// D = A*B + 0  (C = RZ; no accumulator zero-init needed)
__device__ __forceinline__ void mma16816z(float* d, const uint32_t* a, uint32_t b0, uint32_t b1) {
    asm volatile("mma.sync.aligned.m16n8k16.row.col.f32.f16.f16.f32 "
        "{%0,%1,%2,%3}, {%4,%5,%6,%7}, {%8,%9}, {%10,%11,%12,%13};"
        : "=f"(d[0]), "=f"(d[1]), "=f"(d[2]), "=f"(d[3])
        : "r"(a[0]), "r"(a[1]), "r"(a[2]), "r"(a[3]), "r"(b0), "r"(b1),
          "f"(0.f), "f"(0.f), "f"(0.f), "f"(0.f));
}

__global__ void __launch_bounds__(NTHREADS, 1)
msa_hmma12(const float* __restrict__ x, const float* __restrict__ W,
           const float* __restrict__ bias, float* __restrict__ out,
           int nGroups, int step)
{
    extern __shared__ char smem[];
    const uint32_t sb = smem_u32(smem);
    float* sB = reinterpret_cast<float*>(smem + SB_OFF);

    const int h  = blockIdx.x & 1;     // step is even -> h constant per CTA
    const int t  = threadIdx.x;
    const int w  = t >> 5, lane = t & 31;
    const int q2 = 2 * (lane & 3);

    const int nl  = (lane & 7) + ((lane & 16) ? 8 : 0);   // B-frag row (K/W)
    const int cb8 = (lane & 8) ? 16 : 0;
    const int tl  = (lane & 7) + ((lane & 8) ? 8 : 0);    // V trans row piece
    const int vb8 = (lane & 16) ? 16 : 0;

    uint32_t waddr[4], kaddr[4], vaddr[4];
    #pragma unroll
    for (int ks = 0; ks < 4; ks++) {
        waddr[ks] = sb + WT_OFF + SWZ((uint32_t)(nl * 128 + ks * 32 + cb8));
        kaddr[ks] = sb + K_OFF  + SWZ((uint32_t)(nl * 128 + ks * 32 + cb8));
    }
    #pragma unroll
    for (int j = 0; j < 4; j++)
        vaddr[j] = sb + V_OFF + SWZ((uint32_t)(tl * 128 + 32 * j + vb8));

    // X staging per-thread constants: linear f4-index g = k*256+t
    const int c4   = t & 31;
    const int xdst = XT_OFF + (c4 >> 4) * 32768 +
                     (int)SWZ((uint32_t)(w * 128 + (c4 & 15) * 8));

    // ---- one-time: W slice (h fixed) + bias ----
    #pragma unroll 4
    for (int k = 0; k < 24; k++) {
        const int row = 8 * k + w;
        const int grow = (row >> 6) * CH + h * HD + (row & 63);
        float4 v = reinterpret_cast<const float4*>(W + (size_t)grow * CH)[c4];
        *reinterpret_cast<uint2*>(smem + WT_OFF + (c4 >> 4) * 24576 +
                                  SWZ(row * 128 + (c4 & 15) * 8)) =
            make_uint2(h2u(v.x, v.y), h2u(v.z, v.w));
    }
    if (t < 192) sB[t] = bias[(t >> 6) * CH + h * HD + (t & 63)];

    // ---- stage X for this CTA's first group (bulk, MLP=32) ----
    {
        const float4* xg = reinterpret_cast<const float4*>(
            x + (size_t)(blockIdx.x >> 1) * (G * CH)) + t;
        #pragma unroll 8
        for (int k = 0; k < 32; k++) {
            float4 v = xg[k * 256];
            *reinterpret_cast<uint2*>(smem + xdst + k * 1024) =
                make_uint2(h2u(v.x, v.y), h2u(v.z, v.w));
        }
    }

    const int row0 = 32 * w + (lane >> 2);

    // deferred-epilogue state (group g's output written during phase 1 of g+step)
    float oacc[2][8][4];
    float inv[2][2];
    float* prevO = nullptr;

    for (int g = blockIdx.x; g < nGroups; g += step) {
        const int bl = g >> 1;
        const bool hasNext = (g + step) < nGroups;
        const float4* xn = reinterpret_cast<const float4*>(
            x + (size_t)((hasNext ? (g + step) : g) >> 1) * (G * CH)) + t;

        __syncthreads();   // XT staged (prev iter / prologue); K/V free to overwrite

        // ---- deferred output write of PREVIOUS group (overlaps phase-1 issue) ----
        if (prevO) {
            #pragma unroll
            for (int m = 0; m < 2; m++) {
                float* o = prevO + (size_t)(16 * m) * CH;
                #pragma unroll
                for (int jb = 0; jb < 8; jb++) {
                    const int c = 8 * jb + q2;
                    *reinterpret_cast<float2*>(o + c) =
                        make_float2(oacc[m][jb][0] * inv[m][0], oacc[m][jb][1] * inv[m][0]);
                    *reinterpret_cast<float2*>(o + 8 * CH + c) =
                        make_float2(oacc[m][jb][2] * inv[m][1], oacc[m][jb][3] * inv[m][1]);
                }
            }
        }

        // ============ phase 1: QKV GEMM, warp = 32 rows x 192 cols ============
        uint32_t xa[2][8][4];
        #pragma unroll
        for (int m = 0; m < 2; m++)
            #pragma unroll
            for (int ks = 0; ks < 8; ks++) {
                const int r = 32 * w + 16 * m + (lane & 15);
                ldsm4(xa[m][ks], sb + XT_OFF + (ks >> 2) * 32768 +
                      SWZ((uint32_t)(r * 128 + (ks & 3) * 32 + ((lane & 16) ? 16 : 0))));
            }

        uint32_t qa[2][4][4];                // Q as phase-2 A-fragments (in regs)

        #pragma unroll
        for (int chk = 0; chk < 6; chk++) {  // 6 x 32 output cols: QQ KK VV
            float fa[2][4][4];

            #pragma unroll
            for (int ks = 0; ks < 8; ks++)
                #pragma unroll
                for (int j = 0; j < 2; j++) {
                    uint32_t b[4];
                    ldsm4(b, waddr[ks & 3] + (uint32_t)((ks >> 2) * 24576 + chk * 4096 + j * 2048));
                    if (ks == 0) {
                        mma16816z(fa[0][2*j],   xa[0][ks], b[0], b[1]);
                        mma16816z(fa[0][2*j+1], xa[0][ks], b[2], b[3]);
                        mma16816z(fa[1][2*j],   xa[1][ks], b[0], b[1]);
                        mma16816z(fa[1][2*j+1], xa[1][ks], b[2], b[3]);
                    } else {
                        mma16816(fa[0][2*j],   xa[0][ks], b[0], b[1]);
                        mma16816(fa[0][2*j+1], xa[0][ks], b[2], b[3]);
                        mma16816(fa[1][2*j],   xa[1][ks], b[0], b[1]);
                        mma16816(fa[1][2*j+1], xa[1][ks], b[2], b[3]);
                    }
                }

            if (chk < 2) {
                #pragma unroll
                for (int m = 0; m < 2; m++)
                    #pragma unroll
                    for (int kl = 0; kl < 2; kl++) {
                        const float b0 = sB[chk*32 + 16*kl + q2],     b1 = sB[chk*32 + 16*kl + q2 + 1];
                        const float b2 = sB[chk*32 + 16*kl + q2 + 8], b3 = sB[chk*32 + 16*kl + q2 + 9];
                        qa[m][2*chk+kl][0] = h2u((fa[m][2*kl][0]  + b0) * ESC2, (fa[m][2*kl][1]  + b1) * ESC2);
                        qa[m][2*chk+kl][1] = h2u((fa[m][2*kl][2]  + b0) * ESC2, (fa[m][2*kl][3]  + b1) * ESC2);
                        qa[m][2*chk+kl][2] = h2u((fa[m][2*kl+1][0]+ b2) * ESC2, (fa[m][2*kl+1][1]+ b3) * ESC2);
                        qa[m][2*chk+kl][3] = h2u((fa[m][2*kl+1][2]+ b2) * ESC2, (fa[m][2*kl+1][3]+ b3) * ESC2);
                    }
            } else {
                char* dst = smem + (chk < 4 ? K_OFF : V_OFF);
                const int col0 = (chk & 1) * 32;
                #pragma unroll
                for (int m = 0; m < 2; m++) {
                    const int r0 = row0 + 16 * m;
                    #pragma unroll
                    for (int jb = 0; jb < 4; jb++) {
                        const int cc = col0 + 8 * jb + q2;
                        const float b0 = sB[chk*32 + 8*jb + q2], b1 = sB[chk*32 + 8*jb + q2 + 1];
                        *reinterpret_cast<uint32_t*>(dst + SWZ( r0      * 128 + cc * 2)) =
                            h2u(fa[m][jb][0] + b0, fa[m][jb][1] + b1);
                        *reinterpret_cast<uint32_t*>(dst + SWZ((r0 + 8) * 128 + cc * 2)) =
                            h2u(fa[m][jb][2] + b0, fa[m][jb][3] + b1);
                    }
                }
            }
        }
        __syncthreads();   // K/V ready; XT now dead -> staging target

        // ===== phase 2: software-pipelined attention over 8 x 32-token tiles =====
        float rsum[2][2] = {{0.f,0.f},{0.f,0.f}};

        float sacc[2][4][4];
        #pragma unroll
        for (int ks = 0; ks < 4; ks++)          // prologue: S(0)
            #pragma unroll
            for (int j = 0; j < 2; j++) {
                uint32_t b[4];
                ldsm4(b, kaddr[ks] + (uint32_t)(j * 2048));
                if (ks == 0) {
                    mma16816z(sacc[0][2*j],   qa[0][ks], b[0], b[1]);
                    mma16816z(sacc[0][2*j+1], qa[0][ks], b[2], b[3]);
                    mma16816z(sacc[1][2*j],   qa[1][ks], b[0], b[1]);
                    mma16816z(sacc[1][2*j+1], qa[1][ks], b[2], b[3]);
                } else {
                    mma16816(sacc[0][2*j],   qa[0][ks], b[0], b[1]);
                    mma16816(sacc[0][2*j+1], qa[0][ks], b[2], b[3]);
                    mma16816(sacc[1][2*j],   qa[1][ks], b[0], b[1]);
                    mma16816(sacc[1][2*j+1], qa[1][ks], b[2], b[3]);
                }
            }

        #pragma unroll
        for (int i = 0; i < 8; i++) {
            // ---- issue next-X loads early (consumed at end of step) ----
            float4 xv[4];
            if (hasNext) {
                #pragma unroll
                for (int ii = 0; ii < 4; ii++)
                    xv[ii] = xn[(i * 4 + ii) * 256];
            }

            // ---- hoist V-operand loads for PV(i): latency hidden under exp ----
            uint32_t vb[2][4][4];
            #pragma unroll
            for (int ks2 = 0; ks2 < 2; ks2++)
                #pragma unroll
                for (int j = 0; j < 4; j++)
                    ldsm4t(vb[ks2][j], vaddr[j] + (uint32_t)(i * 4096 + ks2 * 2048));

            // ---- exp(sacc_i) -> pf, rsum ----
            uint32_t pf[2][2][4];
            #pragma unroll
            for (int m = 0; m < 2; m++)
                #pragma unroll
                for (int ks2 = 0; ks2 < 2; ks2++) {
                    float e0 = ex2f(sacc[m][2*ks2][0]),   e1 = ex2f(sacc[m][2*ks2][1]);
                    float e2 = ex2f(sacc[m][2*ks2][2]),   e3 = ex2f(sacc[m][2*ks2][3]);
                    float f0 = ex2f(sacc[m][2*ks2+1][0]), f1 = ex2f(sacc[m][2*ks2+1][1]);
                    float f2 = ex2f(sacc[m][2*ks2+1][2]), f3 = ex2f(sacc[m][2*ks2+1][3]);
                    rsum[m][0] += (e0 + e1) + (f0 + f1);
                    rsum[m][1] += (e2 + e3) + (f2 + f3);
                    pf[m][ks2][0] = h2u(e0, e1);
                    pf[m][ks2][1] = h2u(e2, e3);
                    pf[m][ks2][2] = h2u(f0, f1);
                    pf[m][ks2][3] = h2u(f2, f3);
                }

            // ---- S(i+1): overlaps exp above / PV below ----
            if (i < 7) {
                #pragma unroll
                for (int ks = 0; ks < 4; ks++)
                    #pragma unroll
                    for (int j = 0; j < 2; j++) {
                        uint32_t b[4];
                        ldsm4(b, kaddr[ks] + (uint32_t)((i + 1) * 4096 + j * 2048));
                        if (ks == 0) {
                            mma16816z(sacc[0][2*j],   qa[0][ks], b[0], b[1]);
                            mma16816z(sacc[0][2*j+1], qa[0][ks], b[2], b[3]);
                            mma16816z(sacc[1][2*j],   qa[1][ks], b[0], b[1]);
                            mma16816z(sacc[1][2*j+1], qa[1][ks], b[2], b[3]);
                        } else {
                            mma16816(sacc[0][2*j],   qa[0][ks], b[0], b[1]);
                            mma16816(sacc[0][2*j+1], qa[0][ks], b[2], b[3]);
                            mma16816(sacc[1][2*j],   qa[1][ks], b[0], b[1]);
                            mma16816(sacc[1][2*j+1], qa[1][ks], b[2], b[3]);
                        }
                    }
            }

            // ---- PV(i) (V fragments preloaded) ----
            #pragma unroll
            for (int ks2 = 0; ks2 < 2; ks2++)
                #pragma unroll
                for (int j = 0; j < 4; j++) {
                    if (i == 0 && ks2 == 0) {
                        mma16816z(oacc[0][2*j],   pf[0][ks2], vb[ks2][j][0], vb[ks2][j][1]);
                        mma16816z(oacc[0][2*j+1], pf[0][ks2], vb[ks2][j][2], vb[ks2][j][3]);
                        mma16816z(oacc[1][2*j],   pf[1][ks2], vb[ks2][j][0], vb[ks2][j][1]);
                        mma16816z(oacc[1][2*j+1], pf[1][ks2], vb[ks2][j][2], vb[ks2][j][3]);
                    } else {
                        mma16816(oacc[0][2*j],   pf[0][ks2], vb[ks2][j][0], vb[ks2][j][1]);
                        mma16816(oacc[0][2*j+1], pf[0][ks2], vb[ks2][j][2], vb[ks2][j][3]);
                        mma16816(oacc[1][2*j],   pf[1][ks2], vb[ks2][j][0], vb[ks2][j][1]);
                        mma16816(oacc[1][2*j+1], pf[1][ks2], vb[ks2][j][2], vb[ks2][j][3]);
                    }
                }

            // ---- convert + store staged X slice (loads long since landed) ----
            if (hasNext) {
                #pragma unroll
                for (int ii = 0; ii < 4; ii++) {
                    *reinterpret_cast<uint2*>(smem + xdst + (i * 4 + ii) * 1024) =
                        make_uint2(h2u(xv[ii].x, xv[ii].y), h2u(xv[ii].z, xv[ii].w));
                }
            }
        }

        // ---- finalize normalizers; output STGs deferred to next iteration ----
        #pragma unroll
        for (int m = 0; m < 2; m++) {
            float r0s = rsum[m][0], r1s = rsum[m][1];
            r0s += __shfl_xor_sync(0xffffffffu, r0s, 1);
            r0s += __shfl_xor_sync(0xffffffffu, r0s, 2);
            r1s += __shfl_xor_sync(0xffffffffu, r1s, 1);
            r1s += __shfl_xor_sync(0xffffffffu, r1s, 2);
            inv[m][0] = 1.0f / r0s;
            inv[m][1] = 1.0f / r1s;
        }
        prevO = out + ((size_t)(bl * G) + row0) * CH + h * HD;
    }

    // ---- final group's output write ----
    if (prevO) {
        #pragma unroll
        for (int m = 0; m < 2; m++) {
            float* o = prevO + (size_t)(16 * m) * CH;
            #pragma unroll
            for (int jb = 0; jb < 8; jb++) {
                const int c = 8 * jb + q2;
                *reinterpret_cast<float2*>(o + c) =
                    make_float2(oacc[m][jb][0] * inv[m][0], oacc[m][jb][1] * inv[m][0]);
                *reinterpret_cast<float2*>(o + 8 * CH + c) =
                    make_float2(oacc[m][jb][2] * inv[m][1], oacc[m][jb][3] * inv[m][1]);
            }
        }
    }
}

extern "C" void kernel_launch(void* const* d_in, const int* in_sizes, int n_in,
                              void* d_out, int out_size) {
    (void)n_in; (void)out_size;
    const float* x  = (const float*)d_in[0];
    const float* W  = (const float*)d_in[1];
    const float* b  = (const float*)d_in[2];
    float* out = (float*)d_out;

    cudaFuncSetAttribute(msa_hmma12, cudaFuncAttributeMaxDynamicSharedMemorySize, SMEM_BYTES);

    int nbl = in_sizes[0] / (G * CH);   // 512 (b,l) groups
    int nGroups = nbl * 2;

    int dev = 0, sms = 148;
    cudaGetDevice(&dev);
    cudaDeviceGetAttribute(&sms, cudaDevAttrMultiProcessorCount, dev);
    sms &= ~1;                          // even stride -> per-CTA head parity fixed
    if (sms < 2) sms = 2;
    if (sms > nGroups) sms = nGroups;

    msa_hmma12<<<sms, NTHREADS, SMEM_BYTES>>>(x, W, b, out, nGroups, sms);
}

// round 15
// speedup vs baseline: 1.0515x; 1.0515x over previous
#include <cuda_runtime.h>
#include <cuda_fp16.h>
#include <cstdint>
#include <cstddef>

#define G   256
#define CH  128
#define HD  64
#define NTHREADS 256

// ---- smem byte offsets (tiles: [row][64 halves] = 128B rows, SW128 swizzle) ----
#define SB_OFF  0                        // bias: 192 floats
#define XT_OFF  1024                     // 2 x [256][64] fp16 (ch-chunks) = 64 KB
#define WT_OFF  (XT_OFF + 2*32768)       // 2 x [192][64] fp16 (ch-chunks) = 48 KB
#define K_OFF   (WT_OFF + 2*24576)       // [256][64] fp16                 = 32 KB
#define V_OFF   (K_OFF  + 32768)         // [256][64] fp16                 = 32 KB
#define SMEM_BYTES (V_OFF + 32768)       // 181248

#define SWZ(o) ((o) ^ (((o) >> 3) & 0x70))
#define ESC2 0.12751744f                 // (1/sqrt(128)) * log2(e)

__device__ __forceinline__ uint32_t smem_u32(const void* p) {
    uint32_t a;
    asm("{ .reg .u64 t; cvta.to.shared.u64 t, %1; cvt.u32.u64 %0, t; }" : "=r"(a) : "l"(p));
    return a;
}
__device__ __forceinline__ uint32_t h2u(float a, float b) {
    __half2 h = __floats2half2_rn(a, b);
    return *reinterpret_cast<uint32_t*>(&h);
}
__device__ __forceinline__ float ex2f(float x) {
    float r; asm("ex2.approx.f32 %0, %1;" : "=f"(r) : "f"(x)); return r;
}
__device__ __forceinline__ void ldsm4(uint32_t* r, uint32_t addr) {
    asm volatile("ldmatrix.sync.aligned.m8n8.x4.shared.b16 {%0,%1,%2,%3}, [%4];"
                 : "=r"(r[0]), "=r"(r[1]), "=r"(r[2]), "=r"(r[3]) : "r"(addr));
}
__device__ __forceinline__ void ldsm4t(uint32_t* r, uint32_t addr) {
    asm volatile("ldmatrix.sync.aligned.m8n8.x4.trans.shared.b16 {%0,%1,%2,%3}, [%4];"
                 : "=r"(r[0]), "=r"(r[1]), "=r"(r[2]), "=r"(r[3]) : "r"(addr));
}
__device__ __forceinline__ void mma16816(float* d, const uint32_t* a, uint32_t b0, uint32_t b1) {
    asm volatile("mma.sync.aligned.m16n8k16.row.col.f32.f16.f16.f32 "
        "{%0,%1,%2,%3}, {%4,%5,%6,%7}, {%8,%9}, {%0,%1,%2,%3};"
        : "+f"(d[0]), "+f"(d[1]), "+f"(d[2]), "+f"(d[3])
        : "r"(a[0]), "r"(a[1]), "r"(a[2]), "r"(a[3]), "r"(b0), "r"(b1));
}
// D = A*B + 0  (C = RZ; no accumulator zero-init needed)
__device__ __forceinline__ void mma16816z(float* d, const uint32_t* a, uint32_t b0, uint32_t b1) {
    asm volatile("mma.sync.aligned.m16n8k16.row.col.f32.f16.f16.f32 "
        "{%0,%1,%2,%3}, {%4,%5,%6,%7}, {%8,%9}, {%10,%11,%12,%13};"
        : "=f"(d[0]), "=f"(d[1]), "=f"(d[2]), "=f"(d[3])
        : "r"(a[0]), "r"(a[1]), "r"(a[2]), "r"(a[3]), "r"(b0), "r"(b1),
          "f"(0.f), "f"(0.f), "f"(0.f), "f"(0.f));
}

__global__ void __launch_bounds__(NTHREADS, 1)
msa_hmma13(const float* __restrict__ x, const float* __restrict__ W,
           const float* __restrict__ bias, float* __restrict__ out,
           int nGroups, int step)
{
    extern __shared__ char smem[];
    const uint32_t sb = smem_u32(smem);
    float* sB = reinterpret_cast<float*>(smem + SB_OFF);

    const int h  = blockIdx.x & 1;     // step is even -> h constant per CTA
    const int t  = threadIdx.x;
    const int w  = t >> 5, lane = t & 31;
    const int q2 = 2 * (lane & 3);

    const int nl  = (lane & 7) + ((lane & 16) ? 8 : 0);   // B-frag row (K/W)
    const int cb8 = (lane & 8) ? 16 : 0;
    const int tl  = (lane & 7) + ((lane & 8) ? 8 : 0);    // V trans row piece
    const int vb8 = (lane & 16) ? 16 : 0;

    uint32_t waddr[4], kaddr[4], vaddr[4];
    #pragma unroll
    for (int ks = 0; ks < 4; ks++) {
        waddr[ks] = sb + WT_OFF + SWZ((uint32_t)(nl * 128 + ks * 32 + cb8));
        kaddr[ks] = sb + K_OFF  + SWZ((uint32_t)(nl * 128 + ks * 32 + cb8));
    }
    #pragma unroll
    for (int j = 0; j < 4; j++)
        vaddr[j] = sb + V_OFF + SWZ((uint32_t)(tl * 128 + 32 * j + vb8));

    // X staging per-thread constants: linear f4-index g = k*256+t
    const int c4   = t & 31;
    const int xdst = XT_OFF + (c4 >> 4) * 32768 +
                     (int)SWZ((uint32_t)(w * 128 + (c4 & 15) * 8));

    // ---- one-time: W slice (h fixed) + bias ----
    #pragma unroll 4
    for (int k = 0; k < 24; k++) {
        const int row = 8 * k + w;
        const int grow = (row >> 6) * CH + h * HD + (row & 63);
        float4 v = reinterpret_cast<const float4*>(W + (size_t)grow * CH)[c4];
        *reinterpret_cast<uint2*>(smem + WT_OFF + (c4 >> 4) * 24576 +
                                  SWZ(row * 128 + (c4 & 15) * 8)) =
            make_uint2(h2u(v.x, v.y), h2u(v.z, v.w));
    }
    if (t < 192) sB[t] = bias[(t >> 6) * CH + h * HD + (t & 63)];

    // ---- stage X for this CTA's first group (bulk, MLP=32) ----
    {
        const float4* xg = reinterpret_cast<const float4*>(
            x + (size_t)(blockIdx.x >> 1) * (G * CH)) + t;
        #pragma unroll 8
        for (int k = 0; k < 32; k++) {
            float4 v = xg[k * 256];
            *reinterpret_cast<uint2*>(smem + xdst + k * 1024) =
                make_uint2(h2u(v.x, v.y), h2u(v.z, v.w));
        }
    }

    const int row0 = 32 * w + (lane >> 2);

    for (int g = blockIdx.x; g < nGroups; g += step) {
        const int bl = g >> 1;
        const bool hasNext = (g + step) < nGroups;
        const float4* xn = reinterpret_cast<const float4*>(
            x + (size_t)((hasNext ? (g + step) : g) >> 1) * (G * CH)) + t;

        __syncthreads();   // XT staged (prev iter / prologue); K/V free to overwrite

        // ============ phase 1: QKV GEMM, warp = 32 rows x 192 cols ============
        uint32_t xa[2][8][4];
        #pragma unroll
        for (int m = 0; m < 2; m++)
            #pragma unroll
            for (int ks = 0; ks < 8; ks++) {
                const int r = 32 * w + 16 * m + (lane & 15);
                ldsm4(xa[m][ks], sb + XT_OFF + (ks >> 2) * 32768 +
                      SWZ((uint32_t)(r * 128 + (ks & 3) * 32 + ((lane & 16) ? 16 : 0))));
            }

        uint32_t qa[2][4][4];                // Q as phase-2 A-fragments (in regs)

        #pragma unroll
        for (int chk = 0; chk < 6; chk++) {  // 6 x 32 output cols: QQ KK VV
            float fa[2][4][4];

            #pragma unroll
            for (int ks = 0; ks < 8; ks++)
                #pragma unroll
                for (int j = 0; j < 2; j++) {
                    uint32_t b[4];
                    ldsm4(b, waddr[ks & 3] + (uint32_t)((ks >> 2) * 24576 + chk * 4096 + j * 2048));
                    if (ks == 0) {
                        mma16816z(fa[0][2*j],   xa[0][ks], b[0], b[1]);
                        mma16816z(fa[0][2*j+1], xa[0][ks], b[2], b[3]);
                        mma16816z(fa[1][2*j],   xa[1][ks], b[0], b[1]);
                        mma16816z(fa[1][2*j+1], xa[1][ks], b[2], b[3]);
                    } else {
                        mma16816(fa[0][2*j],   xa[0][ks], b[0], b[1]);
                        mma16816(fa[0][2*j+1], xa[0][ks], b[2], b[3]);
                        mma16816(fa[1][2*j],   xa[1][ks], b[0], b[1]);
                        mma16816(fa[1][2*j+1], xa[1][ks], b[2], b[3]);
                    }
                }

            if (chk < 2) {
                #pragma unroll
                for (int m = 0; m < 2; m++)
                    #pragma unroll
                    for (int kl = 0; kl < 2; kl++) {
                        const float b0 = sB[chk*32 + 16*kl + q2],     b1 = sB[chk*32 + 16*kl + q2 + 1];
                        const float b2 = sB[chk*32 + 16*kl + q2 + 8], b3 = sB[chk*32 + 16*kl + q2 + 9];
                        qa[m][2*chk+kl][0] = h2u((fa[m][2*kl][0]  + b0) * ESC2, (fa[m][2*kl][1]  + b1) * ESC2);
                        qa[m][2*chk+kl][1] = h2u((fa[m][2*kl][2]  + b0) * ESC2, (fa[m][2*kl][3]  + b1) * ESC2);
                        qa[m][2*chk+kl][2] = h2u((fa[m][2*kl+1][0]+ b2) * ESC2, (fa[m][2*kl+1][1]+ b3) * ESC2);
                        qa[m][2*chk+kl][3] = h2u((fa[m][2*kl+1][2]+ b2) * ESC2, (fa[m][2*kl+1][3]+ b3) * ESC2);
                    }
            } else {
                char* dst = smem + (chk < 4 ? K_OFF : V_OFF);
                const int col0 = (chk & 1) * 32;
                #pragma unroll
                for (int m = 0; m < 2; m++) {
                    const int r0 = row0 + 16 * m;
                    #pragma unroll
                    for (int jb = 0; jb < 4; jb++) {
                        const int cc = col0 + 8 * jb + q2;
                        const float b0 = sB[chk*32 + 8*jb + q2], b1 = sB[chk*32 + 8*jb + q2 + 1];
                        *reinterpret_cast<uint32_t*>(dst + SWZ( r0      * 128 + cc * 2)) =
                            h2u(fa[m][jb][0] + b0, fa[m][jb][1] + b1);
                        *reinterpret_cast<uint32_t*>(dst + SWZ((r0 + 8) * 128 + cc * 2)) =
                            h2u(fa[m][jb][2] + b0, fa[m][jb][3] + b1);
                    }
                }
            }
        }
        __syncthreads();   // K/V ready; XT now dead -> staging target

        // ===== phase 2: software-pipelined attention over 8 x 32-token tiles =====
        float oacc[2][8][4];
        float rsum[2][2] = {{0.f,0.f},{0.f,0.f}};

        float sacc[2][4][4];
        #pragma unroll
        for (int ks = 0; ks < 4; ks++)          // prologue: S(0)
            #pragma unroll
            for (int j = 0; j < 2; j++) {
                uint32_t b[4];
                ldsm4(b, kaddr[ks] + (uint32_t)(j * 2048));
                if (ks == 0) {
                    mma16816z(sacc[0][2*j],   qa[0][ks], b[0], b[1]);
                    mma16816z(sacc[0][2*j+1], qa[0][ks], b[2], b[3]);
                    mma16816z(sacc[1][2*j],   qa[1][ks], b[0], b[1]);
                    mma16816z(sacc[1][2*j+1], qa[1][ks], b[2], b[3]);
                } else {
                    mma16816(sacc[0][2*j],   qa[0][ks], b[0], b[1]);
                    mma16816(sacc[0][2*j+1], qa[0][ks], b[2], b[3]);
                    mma16816(sacc[1][2*j],   qa[1][ks], b[0], b[1]);
                    mma16816(sacc[1][2*j+1], qa[1][ks], b[2], b[3]);
                }
            }

        #pragma unroll
        for (int i = 0; i < 8; i++) {
            // ---- issue next-X loads early (consumed at end of step) ----
            float4 xv[4];
            if (hasNext) {
                #pragma unroll
                for (int ii = 0; ii < 4; ii++)
                    xv[ii] = xn[(i * 4 + ii) * 256];
            }

            // ---- hoist V-operand loads for PV(i): latency hidden under exp/S(i+1) ----
            uint32_t vb[2][4][4];
            #pragma unroll
            for (int ks2 = 0; ks2 < 2; ks2++)
                #pragma unroll
                for (int j = 0; j < 4; j++)
                    ldsm4t(vb[ks2][j], vaddr[j] + (uint32_t)(i * 4096 + ks2 * 2048));

            // ---- exp(sacc_i) -> pf, rsum ----
            uint32_t pf[2][2][4];
            #pragma unroll
            for (int m = 0; m < 2; m++)
                #pragma unroll
                for (int ks2 = 0; ks2 < 2; ks2++) {
                    float e0 = ex2f(sacc[m][2*ks2][0]),   e1 = ex2f(sacc[m][2*ks2][1]);
                    float e2 = ex2f(sacc[m][2*ks2][2]),   e3 = ex2f(sacc[m][2*ks2][3]);
                    float f0 = ex2f(sacc[m][2*ks2+1][0]), f1 = ex2f(sacc[m][2*ks2+1][1]);
                    float f2 = ex2f(sacc[m][2*ks2+1][2]), f3 = ex2f(sacc[m][2*ks2+1][3]);
                    rsum[m][0] += (e0 + e1) + (f0 + f1);
                    rsum[m][1] += (e2 + e3) + (f2 + f3);
                    pf[m][ks2][0] = h2u(e0, e1);
                    pf[m][ks2][1] = h2u(e2, e3);
                    pf[m][ks2][2] = h2u(f0, f1);
                    pf[m][ks2][3] = h2u(f2, f3);
                }

            // ---- S(i+1): overlaps exp above / PV below ----
            if (i < 7) {
                #pragma unroll
                for (int ks = 0; ks < 4; ks++)
                    #pragma unroll
                    for (int j = 0; j < 2; j++) {
                        uint32_t b[4];
                        ldsm4(b, kaddr[ks] + (uint32_t)((i + 1) * 4096 + j * 2048));
                        if (ks == 0) {
                            mma16816z(sacc[0][2*j],   qa[0][ks], b[0], b[1]);
                            mma16816z(sacc[0][2*j+1], qa[0][ks], b[2], b[3]);
                            mma16816z(sacc[1][2*j],   qa[1][ks], b[0], b[1]);
                            mma16816z(sacc[1][2*j+1], qa[1][ks], b[2], b[3]);
                        } else {
                            mma16816(sacc[0][2*j],   qa[0][ks], b[0], b[1]);
                            mma16816(sacc[0][2*j+1], qa[0][ks], b[2], b[3]);
                            mma16816(sacc[1][2*j],   qa[1][ks], b[0], b[1]);
                            mma16816(sacc[1][2*j+1], qa[1][ks], b[2], b[3]);
                        }
                    }
            }

            // ---- PV(i) (V fragments preloaded) ----
            #pragma unroll
            for (int ks2 = 0; ks2 < 2; ks2++)
                #pragma unroll
                for (int j = 0; j < 4; j++) {
                    if (i == 0 && ks2 == 0) {
                        mma16816z(oacc[0][2*j],   pf[0][ks2], vb[ks2][j][0], vb[ks2][j][1]);
                        mma16816z(oacc[0][2*j+1], pf[0][ks2], vb[ks2][j][2], vb[ks2][j][3]);
                        mma16816z(oacc[1][2*j],   pf[1][ks2], vb[ks2][j][0], vb[ks2][j][1]);
                        mma16816z(oacc[1][2*j+1], pf[1][ks2], vb[ks2][j][2], vb[ks2][j][3]);
                    } else {
                        mma16816(oacc[0][2*j],   pf[0][ks2], vb[ks2][j][0], vb[ks2][j][1]);
                        mma16816(oacc[0][2*j+1], pf[0][ks2], vb[ks2][j][2], vb[ks2][j][3]);
                        mma16816(oacc[1][2*j],   pf[1][ks2], vb[ks2][j][0], vb[ks2][j][1]);
                        mma16816(oacc[1][2*j+1], pf[1][ks2], vb[ks2][j][2], vb[ks2][j][3]);
                    }
                }

            // ---- convert + store staged X slice (loads long since landed) ----
            if (hasNext) {
                #pragma unroll
                for (int ii = 0; ii < 4; ii++) {
                    *reinterpret_cast<uint2*>(smem + xdst + (i * 4 + ii) * 1024) =
                        make_uint2(h2u(xv[ii].x, xv[ii].y), h2u(xv[ii].z, xv[ii].w));
                }
            }
        }

        // normalize + write out (both msubs)
        #pragma unroll
        for (int m = 0; m < 2; m++) {
            float r0s = rsum[m][0], r1s = rsum[m][1];
            r0s += __shfl_xor_sync(0xffffffffu, r0s, 1);
            r0s += __shfl_xor_sync(0xffffffffu, r0s, 2);
            r1s += __shfl_xor_sync(0xffffffffu, r1s, 1);
            r1s += __shfl_xor_sync(0xffffffffu, r1s, 2);
            const float inv0 = 1.0f / r0s, inv1 = 1.0f / r1s;

            float* o = out + ((size_t)(bl * G) + row0 + 16 * m) * CH + h * HD;
            #pragma unroll
            for (int jb = 0; jb < 8; jb++) {
                const int c = 8 * jb + q2;
                *reinterpret_cast<float2*>(o + c) =
                    make_float2(oacc[m][jb][0] * inv0, oacc[m][jb][1] * inv0);
                *reinterpret_cast<float2*>(o + 8 * CH + c) =
                    make_float2(oacc[m][jb][2] * inv1, oacc[m][jb][3] * inv1);
            }
        }
    }
}

extern "C" void kernel_launch(void* const* d_in, const int* in_sizes, int n_in,
                              void* d_out, int out_size) {
    (void)n_in; (void)out_size;
    const float* x  = (const float*)d_in[0];
    const float* W  = (const float*)d_in[1];
    const float* b  = (const float*)d_in[2];
    float* out = (float*)d_out;

    cudaFuncSetAttribute(msa_hmma13, cudaFuncAttributeMaxDynamicSharedMemorySize, SMEM_BYTES);

    int nbl = in_sizes[0] / (G * CH);   // 512 (b,l) groups
    int nGroups = nbl * 2;

    int dev = 0, sms = 148;
    cudaGetDevice(&dev);
    cudaDeviceGetAttribute(&sms, cudaDevAttrMultiProcessorCount, dev);
    sms &= ~1;                          // even stride -> per-CTA head parity fixed
    if (sms < 2) sms = 2;
    if (sms > nGroups) sms = nGroups;

    msa_hmma13<<<sms, NTHREADS, SMEM_BYTES>>>(x, W, b, out, nGroups, sms);
}

// round 16
// speedup vs baseline: 1.1064x; 1.0522x over previous
#include <cuda_runtime.h>
#include <cuda_fp16.h>
#include <cstdint>
#include <cstddef>

#define G   256
#define CH  128
#define HD  64
#define NTHREADS 256

// ---- smem byte offsets (tiles: [row][64 halves] = 128B rows, SW128 swizzle) ----
#define SB_OFF  0                        // bias: 192 floats
#define XT_OFF  1024                     // 2 x [256][64] fp16 (ch-chunks) = 64 KB
#define WT_OFF  (XT_OFF + 2*32768)       // 2 x [192][64] fp16 (ch-chunks) = 48 KB
#define K_OFF   (WT_OFF + 2*24576)       // [256][64] fp16                 = 32 KB
#define V_OFF   (K_OFF  + 32768)         // [256][64] fp16                 = 32 KB
#define SMEM_BYTES (V_OFF + 32768)       // 181248

#define SWZ(o) ((o) ^ (((o) >> 3) & 0x70))
#define ESC2 0.12751744f                 // (1/sqrt(128)) * log2(e)
#define ONES2 0x3C003C00u                // half2(1.0, 1.0)

__device__ __forceinline__ uint32_t smem_u32(const void* p) {
    uint32_t a;
    asm("{ .reg .u64 t; cvta.to.shared.u64 t, %1; cvt.u32.u64 %0, t; }" : "=r"(a) : "l"(p));
    return a;
}
__device__ __forceinline__ uint32_t h2u(float a, float b) {
    __half2 h = __floats2half2_rn(a, b);
    return *reinterpret_cast<uint32_t*>(&h);
}
// packed half2 2^x
__device__ __forceinline__ uint32_t ex2h2(uint32_t x) {
    uint32_t r; asm("ex2.approx.f16x2 %0, %1;" : "=r"(r) : "r"(x)); return r;
}
__device__ __forceinline__ void ldsm4(uint32_t* r, uint32_t addr) {
    asm volatile("ldmatrix.sync.aligned.m8n8.x4.shared.b16 {%0,%1,%2,%3}, [%4];"
                 : "=r"(r[0]), "=r"(r[1]), "=r"(r[2]), "=r"(r[3]) : "r"(addr));
}
__device__ __forceinline__ void ldsm4t(uint32_t* r, uint32_t addr) {
    asm volatile("ldmatrix.sync.aligned.m8n8.x4.trans.shared.b16 {%0,%1,%2,%3}, [%4];"
                 : "=r"(r[0]), "=r"(r[1]), "=r"(r[2]), "=r"(r[3]) : "r"(addr));
}
__device__ __forceinline__ void mma16816(float* d, const uint32_t* a, uint32_t b0, uint32_t b1) {
    asm volatile("mma.sync.aligned.m16n8k16.row.col.f32.f16.f16.f32 "
        "{%0,%1,%2,%3}, {%4,%5,%6,%7}, {%8,%9}, {%0,%1,%2,%3};"
        : "+f"(d[0]), "+f"(d[1]), "+f"(d[2]), "+f"(d[3])
        : "r"(a[0]), "r"(a[1]), "r"(a[2]), "r"(a[3]), "r"(b0), "r"(b1));
}
// D = A*B + 0  (C = RZ; no accumulator zero-init needed)
__device__ __forceinline__ void mma16816z(float* d, const uint32_t* a, uint32_t b0, uint32_t b1) {
    asm volatile("mma.sync.aligned.m16n8k16.row.col.f32.f16.f16.f32 "
        "{%0,%1,%2,%3}, {%4,%5,%6,%7}, {%8,%9}, {%10,%11,%12,%13};"
        : "=f"(d[0]), "=f"(d[1]), "=f"(d[2]), "=f"(d[3])
        : "r"(a[0]), "r"(a[1]), "r"(a[2]), "r"(a[3]), "r"(b0), "r"(b1),
          "f"(0.f), "f"(0.f), "f"(0.f), "f"(0.f));
}

__global__ void __launch_bounds__(NTHREADS, 1)
msa_hmma14(const float* __restrict__ x, const float* __restrict__ W,
           const float* __restrict__ bias, float* __restrict__ out,
           int nGroups, int step)
{
    extern __shared__ char smem[];
    const uint32_t sb = smem_u32(smem);
    float* sB = reinterpret_cast<float*>(smem + SB_OFF);

    const int h  = blockIdx.x & 1;     // step is even -> h constant per CTA
    const int t  = threadIdx.x;
    const int w  = t >> 5, lane = t & 31;
    const int q2 = 2 * (lane & 3);

    const int nl  = (lane & 7) + ((lane & 16) ? 8 : 0);   // B-frag row (K/W)
    const int cb8 = (lane & 8) ? 16 : 0;
    const int tl  = (lane & 7) + ((lane & 8) ? 8 : 0);    // V trans row piece
    const int vb8 = (lane & 16) ? 16 : 0;

    uint32_t waddr[4], kaddr[4], vaddr[4];
    #pragma unroll
    for (int ks = 0; ks < 4; ks++) {
        waddr[ks] = sb + WT_OFF + SWZ((uint32_t)(nl * 128 + ks * 32 + cb8));
        kaddr[ks] = sb + K_OFF  + SWZ((uint32_t)(nl * 128 + ks * 32 + cb8));
    }
    #pragma unroll
    for (int j = 0; j < 4; j++)
        vaddr[j] = sb + V_OFF + SWZ((uint32_t)(tl * 128 + 32 * j + vb8));

    // X staging per-thread constants: linear f4-index g = k*256+t
    const int c4   = t & 31;
    const int xdst = XT_OFF + (c4 >> 4) * 32768 +
                     (int)SWZ((uint32_t)(w * 128 + (c4 & 15) * 8));

    // ---- one-time: W slice (h fixed) + bias ----
    #pragma unroll 4
    for (int k = 0; k < 24; k++) {
        const int row = 8 * k + w;
        const int grow = (row >> 6) * CH + h * HD + (row & 63);
        float4 v = reinterpret_cast<const float4*>(W + (size_t)grow * CH)[c4];
        *reinterpret_cast<uint2*>(smem + WT_OFF + (c4 >> 4) * 24576 +
                                  SWZ(row * 128 + (c4 & 15) * 8)) =
            make_uint2(h2u(v.x, v.y), h2u(v.z, v.w));
    }
    if (t < 192) sB[t] = bias[(t >> 6) * CH + h * HD + (t & 63)];

    // ---- stage X for this CTA's first group (bulk, MLP=32) ----
    {
        const float4* xg = reinterpret_cast<const float4*>(
            x + (size_t)(blockIdx.x >> 1) * (G * CH)) + t;
        #pragma unroll 8
        for (int k = 0; k < 32; k++) {
            float4 v = xg[k * 256];
            *reinterpret_cast<uint2*>(smem + xdst + k * 1024) =
                make_uint2(h2u(v.x, v.y), h2u(v.z, v.w));
        }
    }

    const int row0 = 32 * w + (lane >> 2);

    for (int g = blockIdx.x; g < nGroups; g += step) {
        const int bl = g >> 1;
        const bool hasNext = (g + step) < nGroups;
        const float4* xn = reinterpret_cast<const float4*>(
            x + (size_t)((hasNext ? (g + step) : g) >> 1) * (G * CH)) + t;

        __syncthreads();   // XT staged (prev iter / prologue); K/V free to overwrite

        // ============ phase 1: QKV GEMM, warp = 32 rows x 192 cols ============
        uint32_t xa[2][8][4];
        #pragma unroll
        for (int m = 0; m < 2; m++)
            #pragma unroll
            for (int ks = 0; ks < 8; ks++) {
                const int r = 32 * w + 16 * m + (lane & 15);
                ldsm4(xa[m][ks], sb + XT_OFF + (ks >> 2) * 32768 +
                      SWZ((uint32_t)(r * 128 + (ks & 3) * 32 + ((lane & 16) ? 16 : 0))));
            }

        uint32_t qa[2][4][4];                // Q as phase-2 A-fragments (in regs)

        #pragma unroll
        for (int chk = 0; chk < 6; chk++) {  // 6 x 32 output cols: QQ KK VV
            float fa[2][4][4];

            #pragma unroll
            for (int ks = 0; ks < 8; ks++)
                #pragma unroll
                for (int j = 0; j < 2; j++) {
                    uint32_t b[4];
                    ldsm4(b, waddr[ks & 3] + (uint32_t)((ks >> 2) * 24576 + chk * 4096 + j * 2048));
                    if (ks == 0) {
                        mma16816z(fa[0][2*j],   xa[0][ks], b[0], b[1]);
                        mma16816z(fa[0][2*j+1], xa[0][ks], b[2], b[3]);
                        mma16816z(fa[1][2*j],   xa[1][ks], b[0], b[1]);
                        mma16816z(fa[1][2*j+1], xa[1][ks], b[2], b[3]);
                    } else {
                        mma16816(fa[0][2*j],   xa[0][ks], b[0], b[1]);
                        mma16816(fa[0][2*j+1], xa[0][ks], b[2], b[3]);
                        mma16816(fa[1][2*j],   xa[1][ks], b[0], b[1]);
                        mma16816(fa[1][2*j+1], xa[1][ks], b[2], b[3]);
                    }
                }

            if (chk < 2) {
                #pragma unroll
                for (int m = 0; m < 2; m++)
                    #pragma unroll
                    for (int kl = 0; kl < 2; kl++) {
                        const float b0 = sB[chk*32 + 16*kl + q2],     b1 = sB[chk*32 + 16*kl + q2 + 1];
                        const float b2 = sB[chk*32 + 16*kl + q2 + 8], b3 = sB[chk*32 + 16*kl + q2 + 9];
                        qa[m][2*chk+kl][0] = h2u((fa[m][2*kl][0]  + b0) * ESC2, (fa[m][2*kl][1]  + b1) * ESC2);
                        qa[m][2*chk+kl][1] = h2u((fa[m][2*kl][2]  + b0) * ESC2, (fa[m][2*kl][3]  + b1) * ESC2);
                        qa[m][2*chk+kl][2] = h2u((fa[m][2*kl+1][0]+ b2) * ESC2, (fa[m][2*kl+1][1]+ b3) * ESC2);
                        qa[m][2*chk+kl][3] = h2u((fa[m][2*kl+1][2]+ b2) * ESC2, (fa[m][2*kl+1][3]+ b3) * ESC2);
                    }
            } else {
                char* dst = smem + (chk < 4 ? K_OFF : V_OFF);
                const int col0 = (chk & 1) * 32;
                #pragma unroll
                for (int m = 0; m < 2; m++) {
                    const int r0 = row0 + 16 * m;
                    #pragma unroll
                    for (int jb = 0; jb < 4; jb++) {
                        const int cc = col0 + 8 * jb + q2;
                        const float b0 = sB[chk*32 + 8*jb + q2], b1 = sB[chk*32 + 8*jb + q2 + 1];
                        *reinterpret_cast<uint32_t*>(dst + SWZ( r0      * 128 + cc * 2)) =
                            h2u(fa[m][jb][0] + b0, fa[m][jb][1] + b1);
                        *reinterpret_cast<uint32_t*>(dst + SWZ((r0 + 8) * 128 + cc * 2)) =
                            h2u(fa[m][jb][2] + b0, fa[m][jb][3] + b1);
                    }
                }
            }
        }
        __syncthreads();   // K/V ready; XT now dead -> staging target

        // ===== phase 2: software-pipelined attention over 8 x 32-token tiles =====
        float oacc[2][8][4];
        float racc[2][4];                    // row-sum accumulators (ones-B MMA)

        float sacc[2][4][4];
        #pragma unroll
        for (int ks = 0; ks < 4; ks++)          // prologue: S(0)
            #pragma unroll
            for (int j = 0; j < 2; j++) {
                uint32_t b[4];
                ldsm4(b, kaddr[ks] + (uint32_t)(j * 2048));
                if (ks == 0) {
                    mma16816z(sacc[0][2*j],   qa[0][ks], b[0], b[1]);
                    mma16816z(sacc[0][2*j+1], qa[0][ks], b[2], b[3]);
                    mma16816z(sacc[1][2*j],   qa[1][ks], b[0], b[1]);
                    mma16816z(sacc[1][2*j+1], qa[1][ks], b[2], b[3]);
                } else {
                    mma16816(sacc[0][2*j],   qa[0][ks], b[0], b[1]);
                    mma16816(sacc[0][2*j+1], qa[0][ks], b[2], b[3]);
                    mma16816(sacc[1][2*j],   qa[1][ks], b[0], b[1]);
                    mma16816(sacc[1][2*j+1], qa[1][ks], b[2], b[3]);
                }
            }

        #pragma unroll
        for (int i = 0; i < 8; i++) {
            // ---- issue next-X loads early (consumed at end of step) ----
            float4 xv[4];
            if (hasNext) {
                #pragma unroll
                for (int ii = 0; ii < 4; ii++)
                    xv[ii] = xn[(i * 4 + ii) * 256];
            }

            // ---- 2^s in packed fp16 (pack first, then one ex2 per pair) ----
            uint32_t pf[2][2][4];
            #pragma unroll
            for (int m = 0; m < 2; m++)
                #pragma unroll
                for (int ks2 = 0; ks2 < 2; ks2++) {
                    pf[m][ks2][0] = ex2h2(h2u(sacc[m][2*ks2][0],   sacc[m][2*ks2][1]));
                    pf[m][ks2][1] = ex2h2(h2u(sacc[m][2*ks2][2],   sacc[m][2*ks2][3]));
                    pf[m][ks2][2] = ex2h2(h2u(sacc[m][2*ks2+1][0], sacc[m][2*ks2+1][1]));
                    pf[m][ks2][3] = ex2h2(h2u(sacc[m][2*ks2+1][2], sacc[m][2*ks2+1][3]));
                }

            // ---- row-sums on the tensor pipe: racc += P * ones ----
            #pragma unroll
            for (int m = 0; m < 2; m++)
                #pragma unroll
                for (int ks2 = 0; ks2 < 2; ks2++) {
                    if (i == 0 && ks2 == 0)
                        mma16816z(racc[m], pf[m][ks2], ONES2, ONES2);
                    else
                        mma16816(racc[m], pf[m][ks2], ONES2, ONES2);
                }

            // ---- S(i+1): overlaps exp above / PV below ----
            if (i < 7) {
                #pragma unroll
                for (int ks = 0; ks < 4; ks++)
                    #pragma unroll
                    for (int j = 0; j < 2; j++) {
                        uint32_t b[4];
                        ldsm4(b, kaddr[ks] + (uint32_t)((i + 1) * 4096 + j * 2048));
                        if (ks == 0) {
                            mma16816z(sacc[0][2*j],   qa[0][ks], b[0], b[1]);
                            mma16816z(sacc[0][2*j+1], qa[0][ks], b[2], b[3]);
                            mma16816z(sacc[1][2*j],   qa[1][ks], b[0], b[1]);
                            mma16816z(sacc[1][2*j+1], qa[1][ks], b[2], b[3]);
                        } else {
                            mma16816(sacc[0][2*j],   qa[0][ks], b[0], b[1]);
                            mma16816(sacc[0][2*j+1], qa[0][ks], b[2], b[3]);
                            mma16816(sacc[1][2*j],   qa[1][ks], b[0], b[1]);
                            mma16816(sacc[1][2*j+1], qa[1][ks], b[2], b[3]);
                        }
                    }
            }

            // ---- PV(i) ----
            #pragma unroll
            for (int ks2 = 0; ks2 < 2; ks2++)
                #pragma unroll
                for (int j = 0; j < 4; j++) {
                    uint32_t b[4];
                    ldsm4t(b, vaddr[j] + (uint32_t)(i * 4096 + ks2 * 2048));
                    if (i == 0 && ks2 == 0) {
                        mma16816z(oacc[0][2*j],   pf[0][ks2], b[0], b[1]);
                        mma16816z(oacc[0][2*j+1], pf[0][ks2], b[2], b[3]);
                        mma16816z(oacc[1][2*j],   pf[1][ks2], b[0], b[1]);
                        mma16816z(oacc[1][2*j+1], pf[1][ks2], b[2], b[3]);
                    } else {
                        mma16816(oacc[0][2*j],   pf[0][ks2], b[0], b[1]);
                        mma16816(oacc[0][2*j+1], pf[0][ks2], b[2], b[3]);
                        mma16816(oacc[1][2*j],   pf[1][ks2], b[0], b[1]);
                        mma16816(oacc[1][2*j+1], pf[1][ks2], b[2], b[3]);
                    }
                }

            // ---- convert + store staged X slice (loads long since landed) ----
            if (hasNext) {
                #pragma unroll
                for (int ii = 0; ii < 4; ii++) {
                    *reinterpret_cast<uint2*>(smem + xdst + (i * 4 + ii) * 1024) =
                        make_uint2(h2u(xv[ii].x, xv[ii].y), h2u(xv[ii].z, xv[ii].w));
                }
            }
        }

        // normalize + write out (row sums direct from racc; no shfl needed)
        #pragma unroll
        for (int m = 0; m < 2; m++) {
            const float inv0 = 1.0f / racc[m][0];
            const float inv1 = 1.0f / racc[m][2];

            float* o = out + ((size_t)(bl * G) + row0 + 16 * m) * CH + h * HD;
            #pragma unroll
            for (int jb = 0; jb < 8; jb++) {
                const int c = 8 * jb + q2;
                *reinterpret_cast<float2*>(o + c) =
                    make_float2(oacc[m][jb][0] * inv0, oacc[m][jb][1] * inv0);
                *reinterpret_cast<float2*>(o + 8 * CH + c) =
                    make_float2(oacc[m][jb][2] * inv1, oacc[m][jb][3] * inv1);
            }
        }
    }
}

extern "C" void kernel_launch(void* const* d_in, const int* in_sizes, int n_in,
                              void* d_out, int out_size) {
    (void)n_in; (void)out_size;
    const float* x  = (const float*)d_in[0];
    const float* W  = (const float*)d_in[1];
    const float* b  = (const float*)d_in[2];
    float* out = (float*)d_out;

    cudaFuncSetAttribute(msa_hmma14, cudaFuncAttributeMaxDynamicSharedMemorySize, SMEM_BYTES);

    int nbl = in_sizes[0] / (G * CH);   // 512 (b,l) groups
    int nGroups = nbl * 2;

    int dev = 0, sms = 148;
    cudaGetDevice(&dev);
    cudaDeviceGetAttribute(&sms, cudaDevAttrMultiProcessorCount, dev);
    sms &= ~1;                          // even stride -> per-CTA head parity fixed
    if (sms < 2) sms = 2;
    if (sms > nGroups) sms = nGroups;

    msa_hmma14<<<sms, NTHREADS, SMEM_BYTES>>>(x, W, b, out, nGroups, sms);
}

// round 17
// speedup vs baseline: 1.1170x; 1.0096x over previous
#include <cuda_runtime.h>
#include <cuda_fp16.h>
#include <cstdint>
#include <cstddef>

#define G   256
#define CH  128
#define HD  64
#define NTHREADS 256

// ---- smem byte offsets (tiles: [row][64 halves] = 128B rows, SW128 swizzle) ----
#define SB_OFF  0                        // bias: 192 floats
#define XT_OFF  1024                     // 2 x [256][64] fp16 (ch-chunks) = 64 KB
#define WT_OFF  (XT_OFF + 2*32768)       // 2 x [192][64] fp16 (ch-chunks) = 48 KB
#define K_OFF   (WT_OFF + 2*24576)       // [256][64] fp16                 = 32 KB
#define V_OFF   (K_OFF  + 32768)         // [256][64] fp16                 = 32 KB
#define SMEM_BYTES (V_OFF + 32768)       // 181248

#define SWZ(o) ((o) ^ (((o) >> 3) & 0x70))
#define ESC2 0.12751744f                 // (1/sqrt(128)) * log2(e)
#define ONES2 0x3C003C00u                // half2(1.0, 1.0)

__device__ __forceinline__ uint32_t smem_u32(const void* p) {
    uint32_t a;
    asm("{ .reg .u64 t; cvta.to.shared.u64 t, %1; cvt.u32.u64 %0, t; }" : "=r"(a) : "l"(p));
    return a;
}
__device__ __forceinline__ uint32_t h2u(float a, float b) {
    __half2 h = __floats2half2_rn(a, b);
    return *reinterpret_cast<uint32_t*>(&h);
}
// packed half2 2^x
__device__ __forceinline__ uint32_t ex2h2(uint32_t x) {
    uint32_t r; asm("ex2.approx.f16x2 %0, %1;" : "=r"(r) : "r"(x)); return r;
}
__device__ __forceinline__ void ldsm4(uint32_t* r, uint32_t addr) {
    asm volatile("ldmatrix.sync.aligned.m8n8.x4.shared.b16 {%0,%1,%2,%3}, [%4];"
                 : "=r"(r[0]), "=r"(r[1]), "=r"(r[2]), "=r"(r[3]) : "r"(addr));
}
__device__ __forceinline__ void ldsm4t(uint32_t* r, uint32_t addr) {
    asm volatile("ldmatrix.sync.aligned.m8n8.x4.trans.shared.b16 {%0,%1,%2,%3}, [%4];"
                 : "=r"(r[0]), "=r"(r[1]), "=r"(r[2]), "=r"(r[3]) : "r"(addr));
}
// warp-cooperative store of 4 8x8 fp16 matrices (inverse of ldsm4)
__device__ __forceinline__ void stsm4(uint32_t addr, uint32_t d0, uint32_t d1,
                                      uint32_t d2, uint32_t d3) {
    asm volatile("stmatrix.sync.aligned.m8n8.x4.shared.b16 [%0], {%1,%2,%3,%4};"
                 :: "r"(addr), "r"(d0), "r"(d1), "r"(d2), "r"(d3) : "memory");
}
__device__ __forceinline__ void mma16816(float* d, const uint32_t* a, uint32_t b0, uint32_t b1) {
    asm volatile("mma.sync.aligned.m16n8k16.row.col.f32.f16.f16.f32 "
        "{%0,%1,%2,%3}, {%4,%5,%6,%7}, {%8,%9}, {%0,%1,%2,%3};"
        : "+f"(d[0]), "+f"(d[1]), "+f"(d[2]), "+f"(d[3])
        : "r"(a[0]), "r"(a[1]), "r"(a[2]), "r"(a[3]), "r"(b0), "r"(b1));
}
// D = A*B + 0  (C = RZ; no accumulator zero-init needed)
__device__ __forceinline__ void mma16816z(float* d, const uint32_t* a, uint32_t b0, uint32_t b1) {
    asm volatile("mma.sync.aligned.m16n8k16.row.col.f32.f16.f16.f32 "
        "{%0,%1,%2,%3}, {%4,%5,%6,%7}, {%8,%9}, {%10,%11,%12,%13};"
        : "=f"(d[0]), "=f"(d[1]), "=f"(d[2]), "=f"(d[3])
        : "r"(a[0]), "r"(a[1]), "r"(a[2]), "r"(a[3]), "r"(b0), "r"(b1),
          "f"(0.f), "f"(0.f), "f"(0.f), "f"(0.f));
}

__global__ void __launch_bounds__(NTHREADS, 1)
msa_hmma15(const float* __restrict__ x, const float* __restrict__ W,
           const float* __restrict__ bias, float* __restrict__ out,
           int nGroups, int step)
{
    extern __shared__ char smem[];
    const uint32_t sb = smem_u32(smem);
    float* sB = reinterpret_cast<float*>(smem + SB_OFF);

    const int h  = blockIdx.x & 1;     // step is even -> h constant per CTA
    const int t  = threadIdx.x;
    const int w  = t >> 5, lane = t & 31;
    const int q2 = 2 * (lane & 3);

    const int nl  = (lane & 7) + ((lane & 16) ? 8 : 0);   // B-frag row (K/W)
    const int cb8 = (lane & 8) ? 16 : 0;
    const int tl  = (lane & 7) + ((lane & 8) ? 8 : 0);    // V trans row piece
    const int vb8 = (lane & 16) ? 16 : 0;

    uint32_t waddr[4], kaddr[4], vaddr[4];
    #pragma unroll
    for (int ks = 0; ks < 4; ks++) {
        waddr[ks] = sb + WT_OFF + SWZ((uint32_t)(nl * 128 + ks * 32 + cb8));
        kaddr[ks] = sb + K_OFF  + SWZ((uint32_t)(nl * 128 + ks * 32 + cb8));
    }
    #pragma unroll
    for (int j = 0; j < 4; j++)
        vaddr[j] = sb + V_OFF + SWZ((uint32_t)(tl * 128 + 32 * j + vb8));

    // STSM per-lane address pieces: lane l supplies row (l&7) of matrix (l>>3)
    //   lanepart = (l&7)*128 + 16*(l>>3); col0 toggles +64 (bit6, pre-swizzle)
    const uint32_t lanepart = (uint32_t)((lane & 7) * 128 + 16 * (lane >> 3));
    const uint32_t sts0 = SWZ(lanepart);          // chk even (col0 = 0)
    const uint32_t sts1 = SWZ(lanepart + 64);     // chk odd  (col0 = 32 halves)

    // X staging per-thread constants: linear f4-index g = k*256+t
    const int c4   = t & 31;
    const int xdst = XT_OFF + (c4 >> 4) * 32768 +
                     (int)SWZ((uint32_t)(w * 128 + (c4 & 15) * 8));

    // ---- one-time: W slice (h fixed) + bias ----
    #pragma unroll 4
    for (int k = 0; k < 24; k++) {
        const int row = 8 * k + w;
        const int grow = (row >> 6) * CH + h * HD + (row & 63);
        float4 v = reinterpret_cast<const float4*>(W + (size_t)grow * CH)[c4];
        *reinterpret_cast<uint2*>(smem + WT_OFF + (c4 >> 4) * 24576 +
                                  SWZ(row * 128 + (c4 & 15) * 8)) =
            make_uint2(h2u(v.x, v.y), h2u(v.z, v.w));
    }
    if (t < 192) sB[t] = bias[(t >> 6) * CH + h * HD + (t & 63)];

    // ---- stage X for this CTA's first group (bulk, MLP=32) ----
    {
        const float4* xg = reinterpret_cast<const float4*>(
            x + (size_t)(blockIdx.x >> 1) * (G * CH)) + t;
        #pragma unroll 8
        for (int k = 0; k < 32; k++) {
            float4 v = xg[k * 256];
            *reinterpret_cast<uint2*>(smem + xdst + k * 1024) =
                make_uint2(h2u(v.x, v.y), h2u(v.z, v.w));
        }
    }

    const int row0 = 32 * w + (lane >> 2);

    for (int g = blockIdx.x; g < nGroups; g += step) {
        const int bl = g >> 1;
        const bool hasNext = (g + step) < nGroups;
        const float4* xn = reinterpret_cast<const float4*>(
            x + (size_t)((hasNext ? (g + step) : g) >> 1) * (G * CH)) + t;

        __syncthreads();   // XT staged (prev iter / prologue); K/V free to overwrite

        // ============ phase 1: QKV GEMM, warp = 32 rows x 192 cols ============
        uint32_t xa[2][8][4];
        #pragma unroll
        for (int m = 0; m < 2; m++)
            #pragma unroll
            for (int ks = 0; ks < 8; ks++) {
                const int r = 32 * w + 16 * m + (lane & 15);
                ldsm4(xa[m][ks], sb + XT_OFF + (ks >> 2) * 32768 +
                      SWZ((uint32_t)(r * 128 + (ks & 3) * 32 + ((lane & 16) ? 16 : 0))));
            }

        uint32_t qa[2][4][4];                // Q as phase-2 A-fragments (in regs)

        #pragma unroll
        for (int chk = 0; chk < 6; chk++) {  // 6 x 32 output cols: QQ KK VV
            float fa[2][4][4];

            #pragma unroll
            for (int ks = 0; ks < 8; ks++)
                #pragma unroll
                for (int j = 0; j < 2; j++) {
                    uint32_t b[4];
                    ldsm4(b, waddr[ks & 3] + (uint32_t)((ks >> 2) * 24576 + chk * 4096 + j * 2048));
                    if (ks == 0) {
                        mma16816z(fa[0][2*j],   xa[0][ks], b[0], b[1]);
                        mma16816z(fa[0][2*j+1], xa[0][ks], b[2], b[3]);
                        mma16816z(fa[1][2*j],   xa[1][ks], b[0], b[1]);
                        mma16816z(fa[1][2*j+1], xa[1][ks], b[2], b[3]);
                    } else {
                        mma16816(fa[0][2*j],   xa[0][ks], b[0], b[1]);
                        mma16816(fa[0][2*j+1], xa[0][ks], b[2], b[3]);
                        mma16816(fa[1][2*j],   xa[1][ks], b[0], b[1]);
                        mma16816(fa[1][2*j+1], xa[1][ks], b[2], b[3]);
                    }
                }

            if (chk < 2) {
                #pragma unroll
                for (int m = 0; m < 2; m++)
                    #pragma unroll
                    for (int kl = 0; kl < 2; kl++) {
                        const float b0 = sB[chk*32 + 16*kl + q2],     b1 = sB[chk*32 + 16*kl + q2 + 1];
                        const float b2 = sB[chk*32 + 16*kl + q2 + 8], b3 = sB[chk*32 + 16*kl + q2 + 9];
                        qa[m][2*chk+kl][0] = h2u((fa[m][2*kl][0]  + b0) * ESC2, (fa[m][2*kl][1]  + b1) * ESC2);
                        qa[m][2*chk+kl][1] = h2u((fa[m][2*kl][2]  + b0) * ESC2, (fa[m][2*kl][3]  + b1) * ESC2);
                        qa[m][2*chk+kl][2] = h2u((fa[m][2*kl+1][0]+ b2) * ESC2, (fa[m][2*kl+1][1]+ b3) * ESC2);
                        qa[m][2*chk+kl][3] = h2u((fa[m][2*kl+1][2]+ b2) * ESC2, (fa[m][2*kl+1][3]+ b3) * ESC2);
                    }
            } else {
                // K/V epilogue via stmatrix: bytes/addresses identical to scalar STS
                const uint32_t dstBase = sb + (uint32_t)(chk < 4 ? K_OFF : V_OFF) +
                                         (uint32_t)(4096 * w) +
                                         ((chk & 1) ? sts1 : sts0);
                #pragma unroll
                for (int m = 0; m < 2; m++) {
                    uint32_t p0[4], p1[4];
                    #pragma unroll
                    for (int jb = 0; jb < 4; jb++) {
                        const float b0 = sB[chk*32 + 8*jb + q2], b1 = sB[chk*32 + 8*jb + q2 + 1];
                        p0[jb] = h2u(fa[m][jb][0] + b0, fa[m][jb][1] + b1);   // rows r0..r0+7
                        p1[jb] = h2u(fa[m][jb][2] + b0, fa[m][jb][3] + b1);   // rows r0+8..r0+15
                    }
                    stsm4(dstBase + (uint32_t)(2048 * m),        p0[0], p0[1], p0[2], p0[3]);
                    stsm4(dstBase + (uint32_t)(2048 * m + 1024), p1[0], p1[1], p1[2], p1[3]);
                }
            }
        }
        __syncthreads();   // K/V ready; XT now dead -> staging target

        // ===== phase 2: software-pipelined attention over 8 x 32-token tiles =====
        float oacc[2][8][4];
        float racc[2][4];                    // row-sum accumulators (ones-B MMA)

        float sacc[2][4][4];
        #pragma unroll
        for (int ks = 0; ks < 4; ks++)          // prologue: S(0)
            #pragma unroll
            for (int j = 0; j < 2; j++) {
                uint32_t b[4];
                ldsm4(b, kaddr[ks] + (uint32_t)(j * 2048));
                if (ks == 0) {
                    mma16816z(sacc[0][2*j],   qa[0][ks], b[0], b[1]);
                    mma16816z(sacc[0][2*j+1], qa[0][ks], b[2], b[3]);
                    mma16816z(sacc[1][2*j],   qa[1][ks], b[0], b[1]);
                    mma16816z(sacc[1][2*j+1], qa[1][ks], b[2], b[3]);
                } else {
                    mma16816(sacc[0][2*j],   qa[0][ks], b[0], b[1]);
                    mma16816(sacc[0][2*j+1], qa[0][ks], b[2], b[3]);
                    mma16816(sacc[1][2*j],   qa[1][ks], b[0], b[1]);
                    mma16816(sacc[1][2*j+1], qa[1][ks], b[2], b[3]);
                }
            }

        #pragma unroll
        for (int i = 0; i < 8; i++) {
            // ---- issue next-X loads early (consumed at end of step) ----
            float4 xv[4];
            if (hasNext) {
                #pragma unroll
                for (int ii = 0; ii < 4; ii++)
                    xv[ii] = xn[(i * 4 + ii) * 256];
            }

            // ---- 2^s in packed fp16 (pack first, then one ex2 per pair) ----
            uint32_t pf[2][2][4];
            #pragma unroll
            for (int m = 0; m < 2; m++)
                #pragma unroll
                for (int ks2 = 0; ks2 < 2; ks2++) {
                    pf[m][ks2][0] = ex2h2(h2u(sacc[m][2*ks2][0],   sacc[m][2*ks2][1]));
                    pf[m][ks2][1] = ex2h2(h2u(sacc[m][2*ks2][2],   sacc[m][2*ks2][3]));
                    pf[m][ks2][2] = ex2h2(h2u(sacc[m][2*ks2+1][0], sacc[m][2*ks2+1][1]));
                    pf[m][ks2][3] = ex2h2(h2u(sacc[m][2*ks2+1][2], sacc[m][2*ks2+1][3]));
                }

            // ---- S(i+1): independent of pf -> fills ex2 latency ----
            if (i < 7) {
                #pragma unroll
                for (int ks = 0; ks < 4; ks++)
                    #pragma unroll
                    for (int j = 0; j < 2; j++) {
                        uint32_t b[4];
                        ldsm4(b, kaddr[ks] + (uint32_t)((i + 1) * 4096 + j * 2048));
                        if (ks == 0) {
                            mma16816z(sacc[0][2*j],   qa[0][ks], b[0], b[1]);
                            mma16816z(sacc[0][2*j+1], qa[0][ks], b[2], b[3]);
                            mma16816z(sacc[1][2*j],   qa[1][ks], b[0], b[1]);
                            mma16816z(sacc[1][2*j+1], qa[1][ks], b[2], b[3]);
                        } else {
                            mma16816(sacc[0][2*j],   qa[0][ks], b[0], b[1]);
                            mma16816(sacc[0][2*j+1], qa[0][ks], b[2], b[3]);
                            mma16816(sacc[1][2*j],   qa[1][ks], b[0], b[1]);
                            mma16816(sacc[1][2*j+1], qa[1][ks], b[2], b[3]);
                        }
                    }
            }

            // ---- row-sums on the tensor pipe: racc += P * ones ----
            #pragma unroll
            for (int m = 0; m < 2; m++)
                #pragma unroll
                for (int ks2 = 0; ks2 < 2; ks2++) {
                    if (i == 0 && ks2 == 0)
                        mma16816z(racc[m], pf[m][ks2], ONES2, ONES2);
                    else
                        mma16816(racc[m], pf[m][ks2], ONES2, ONES2);
                }

            // ---- PV(i) ----
            #pragma unroll
            for (int ks2 = 0; ks2 < 2; ks2++)
                #pragma unroll
                for (int j = 0; j < 4; j++) {
                    uint32_t b[4];
                    ldsm4t(b, vaddr[j] + (uint32_t)(i * 4096 + ks2 * 2048));
                    if (i == 0 && ks2 == 0) {
                        mma16816z(oacc[0][2*j],   pf[0][ks2], b[0], b[1]);
                        mma16816z(oacc[0][2*j+1], pf[0][ks2], b[2], b[3]);
                        mma16816z(oacc[1][2*j],   pf[1][ks2], b[0], b[1]);
                        mma16816z(oacc[1][2*j+1], pf[1][ks2], b[2], b[3]);
                    } else {
                        mma16816(oacc[0][2*j],   pf[0][ks2], b[0], b[1]);
                        mma16816(oacc[0][2*j+1], pf[0][ks2], b[2], b[3]);
                        mma16816(oacc[1][2*j],   pf[1][ks2], b[0], b[1]);
                        mma16816(oacc[1][2*j+1], pf[1][ks2], b[2], b[3]);
                    }
                }

            // ---- convert + store staged X slice (loads long since landed) ----
            if (hasNext) {
                #pragma unroll
                for (int ii = 0; ii < 4; ii++) {
                    *reinterpret_cast<uint2*>(smem + xdst + (i * 4 + ii) * 1024) =
                        make_uint2(h2u(xv[ii].x, xv[ii].y), h2u(xv[ii].z, xv[ii].w));
                }
            }
        }

        // normalize + write out (row sums direct from racc; no shfl needed)
        #pragma unroll
        for (int m = 0; m < 2; m++) {
            const float inv0 = 1.0f / racc[m][0];
            const float inv1 = 1.0f / racc[m][2];

            float* o = out + ((size_t)(bl * G) + row0 + 16 * m) * CH + h * HD;
            #pragma unroll
            for (int jb = 0; jb < 8; jb++) {
                const int c = 8 * jb + q2;
                *reinterpret_cast<float2*>(o + c) =
                    make_float2(oacc[m][jb][0] * inv0, oacc[m][jb][1] * inv0);
                *reinterpret_cast<float2*>(o + 8 * CH + c) =
                    make_float2(oacc[m][jb][2] * inv1, oacc[m][jb][3] * inv1);
            }
        }
    }
}

extern "C" void kernel_launch(void* const* d_in, const int* in_sizes, int n_in,
                              void* d_out, int out_size) {
    (void)n_in; (void)out_size;
    const float* x  = (const float*)d_in[0];
    const float* W  = (const float*)d_in[1];
    const float* b  = (const float*)d_in[2];
    float* out = (float*)d_out;

    cudaFuncSetAttribute(msa_hmma15, cudaFuncAttributeMaxDynamicSharedMemorySize, SMEM_BYTES);

    int nbl = in_sizes[0] / (G * CH);   // 512 (b,l) groups
    int nGroups = nbl * 2;

    int dev = 0, sms = 148;
    cudaGetDevice(&dev);
    cudaDeviceGetAttribute(&sms, cudaDevAttrMultiProcessorCount, dev);
    sms &= ~1;                          // even stride -> per-CTA head parity fixed
    if (sms < 2) sms = 2;
    if (sms > nGroups) sms = nGroups;

    msa_hmma15<<<sms, NTHREADS, SMEM_BYTES>>>(x, W, b, out, nGroups, sms);
}